// round 15
// baseline (speedup 1.0000x reference)
#include <cuda_runtime.h>

#define N_NODES 25000
#define N_EDGES 100000
#define NODE_IN 8
#define HID 32

// Scratch (device globals — allocation is forbidden). Zero-initialized at load;
// every kernel_launch call restores them to zero, so no per-call zeroing pass.
__device__ float g_h1[N_NODES * HID];
__device__ float g_h2[N_NODES * HID];
__device__ float g_agg[N_NODES * HID];
__device__ float g_cnt[N_NODES];
__device__ float g_inv[N_NODES];
__device__ int2  g_sd[N_EDGES];     // packed {src, dst}
__device__ int   g_bad64 = 0;       // raised (never lowered) if edge_index is int32

// ---------------------------------------------------------------------------
// PDL primitives (sm_90+)
// ---------------------------------------------------------------------------
__device__ __forceinline__ void gdc_wait()   { asm volatile("griddepcontrol.wait;" ::: "memory"); }
__device__ __forceinline__ void gdc_launch() { asm volatile("griddepcontrol.launch_dependents;" ::: "memory"); }

// ---------------------------------------------------------------------------
// Packed f32x2 helpers (Blackwell FFMA2 — only reachable via PTX)
// ---------------------------------------------------------------------------
__device__ __forceinline__ unsigned long long pk2(float lo, float hi) {
    unsigned long long r;
    asm("mov.b64 %0, {%1, %2};" : "=l"(r) : "f"(lo), "f"(hi));
    return r;
}
__device__ __forceinline__ void upk2(unsigned long long v, float& lo, float& hi) {
    asm("mov.b64 {%0, %1}, %2;" : "=f"(lo), "=f"(hi) : "l"(v));
}
__device__ __forceinline__ unsigned long long fma2(unsigned long long a,
                                                   unsigned long long b,
                                                   unsigned long long c) {
    unsigned long long d;
    asm("fma.rn.f32x2 %0, %1, %2, %3;" : "=l"(d) : "l"(a), "l"(b), "l"(c));
    return d;
}

// ---------------------------------------------------------------------------
// Detect index dtype (read-only). int64 data keeps flag 0; int32 raises it.
// Reads first N_EDGES words as int64 — spans exactly the int32 buffer or the
// src half of an int64 buffer, no OOB either way.
// ---------------------------------------------------------------------------
__global__ void detect_kernel(const void* __restrict__ ei) {
    int i = blockIdx.x * blockDim.x + threadIdx.x;
    if (i < N_EDGES) {
        long long v = ((const long long*)ei)[i];
        if (v < 0 || v >= N_NODES) g_bad64 = 1;
    }
    gdc_launch();
}

// ---------------------------------------------------------------------------
// Convert indices (dtype per flag, clamped) + accumulate in-degrees.
// g_cnt enters zeroed (node1 restored it at the end of the previous call).
// ---------------------------------------------------------------------------
__global__ void convert_degree_kernel(const void* __restrict__ ei) {
    gdc_wait();                                   // g_bad64 from detect
    int e = blockIdx.x * blockDim.x + threadIdx.x;
    if (e < N_EDGES) {
        const bool is64 = (g_bad64 == 0);
        long long s, d;
        if (is64) {
            s = ((const long long*)ei)[e];
            d = ((const long long*)ei)[N_EDGES + e];
        } else {
            s = ((const int*)ei)[e];
            d = ((const int*)ei)[N_EDGES + e];
        }
        int si = (int)s, di = (int)d;
        si = si < 0 ? 0 : (si >= N_NODES ? N_NODES - 1 : si);
        di = di < 0 ? 0 : (di >= N_NODES ? N_NODES - 1 : di);
        g_sd[e] = make_int2(si, di);
        atomicAdd(&g_cnt[di], 1.0f);
    }
    gdc_launch();
}

// ---------------------------------------------------------------------------
// Edge kernel: one warp per GROUP of ET=6 edges (grid-stride).
// Round-13 profile: L1tex (weight LDS wavefronts) is the binding pipe, not
// occupancy — ET=6 amortizes each weight LDS over 6 edges (wf/edge 40->26.7).
// lane o computes msg[o] = sum_i h[src,i] * relu( ea . W[:, i*32+o] + b )
// All smem operands are LDS.128; x staged per warp (double-buffered).
// SEL: 0 -> x, 1 -> g_h1, 2 -> g_h2.
// ---------------------------------------------------------------------------
template <int IN, int SEL>
__global__ void __launch_bounds__(256, 3)
edge_kernel(const float* __restrict__ x,
            const float* __restrict__ ea,
            const float* __restrict__ w_mlp,  // [4, IN*HID] row-major
            const float* __restrict__ b_mlp)  // [IN*HID]
{
    constexpr int COLS  = IN * HID;
    constexpr int PAIRS = IN / 2;
    constexpr int PP    = PAIRS / 2;            // pair-pairs
    constexpr int ET    = 6;
    constexpr int NW    = 8;                    // warps per 256-thread block
    static_assert(PAIRS % 2 == 0, "even pair count");

    __shared__ ulonglong2 ws4[PAIRS * 2 * HID];
    __shared__ ulonglong2 bs4[PP * HID];
    __shared__ __align__(16) float xs[2][NW][ET * HID];  // double-buffered x rows

    // ---- independent prologue (external inputs only; overlaps via PDL) ----
    for (int idx = threadIdx.x; idx < PAIRS * 2 * HID; idx += blockDim.x) {
        int o = idx & (HID - 1);
        int q = (idx >> 5) & 1;
        int p = idx >> 6;
        ws4[idx] = make_ulonglong2(
            pk2(w_mlp[(2*q  )*COLS + (2*p)*HID + o], w_mlp[(2*q  )*COLS + (2*p+1)*HID + o]),
            pk2(w_mlp[(2*q+1)*COLS + (2*p)*HID + o], w_mlp[(2*q+1)*COLS + (2*p+1)*HID + o]));
    }
    for (int idx = threadIdx.x; idx < PP * HID; idx += blockDim.x) {
        int o  = idx & (HID - 1);
        int pp = idx >> 5;
        bs4[idx] = make_ulonglong2(
            pk2(b_mlp[(4*pp    )*HID + o], b_mlp[(4*pp + 1)*HID + o]),
            pk2(b_mlp[(4*pp + 2)*HID + o], b_mlp[(4*pp + 3)*HID + o]));
    }
    __syncthreads();

    gdc_wait();   // g_sd / h-buffer / zeroed g_agg from predecessors

    const int lane    = (int)(threadIdx.x & 31u);
    const int wl      = (int)(threadIdx.x >> 5);        // warp within block
    const int warp    = (int)((blockIdx.x * blockDim.x + threadIdx.x) >> 5);
    const int nwarps  = (int)((gridDim.x * blockDim.x) >> 5);
    const int ngroups = (N_EDGES + ET - 1) / ET;

    int buf = 0;
    for (int g = warp; g < ngroups; g += nwarps, buf ^= 1) {
        const int e0 = g * ET;

        int dst[ET];
        unsigned long long eap[ET][4];
        #pragma unroll
        for (int j = 0; j < ET; ++j) {
            int e = e0 + j;
            e = e < N_EDGES ? e : N_EDGES - 1;   // clamp loads; atomic guarded
            const int2 sd = g_sd[e];
            dst[j] = sd.y;
            float4 v = *(const float4*)(ea + 4 * e);
            eap[j][0] = pk2(v.x, v.x);
            eap[j][1] = pk2(v.y, v.y);
            eap[j][2] = pk2(v.z, v.z);
            eap[j][3] = pk2(v.w, v.w);
            float xvj;
            if (SEL == 0)      xvj = x[sd.x * IN + (lane & (IN - 1))];
            else if (SEL == 1) xvj = g_h1[sd.x * IN + (lane & (IN - 1))];
            else               xvj = g_h2[sd.x * IN + (lane & (IN - 1))];
            xs[buf][wl][j * HID + lane] = xvj;
        }
        __syncwarp();
        const ulonglong2* xr = (const ulonglong2*)xs[buf][wl];

        unsigned long long msg2[ET];
        #pragma unroll
        for (int j = 0; j < ET; ++j) msg2[j] = 0ull;   // bits(0,0) == (0.f,0.f)

        #pragma unroll
        for (int pp = 0; pp < PP; ++pp) {
            const ulonglong2 bq  = bs4[pp * HID + lane];
            const ulonglong2 wA0 = ws4[(4*pp + 0) * HID + lane];
            const ulonglong2 wB0 = ws4[(4*pp + 1) * HID + lane];
            const ulonglong2 wA1 = ws4[(4*pp + 2) * HID + lane];
            const ulonglong2 wB1 = ws4[(4*pp + 3) * HID + lane];
            #pragma unroll
            for (int j = 0; j < ET; ++j) {
                const ulonglong2 xq = xr[j * (HID / 4) + pp];  // two x-pairs
                unsigned long long a0 = fma2(eap[j][0], wA0.x, bq.x);
                a0 = fma2(eap[j][1], wA0.y, a0);
                a0 = fma2(eap[j][2], wB0.x, a0);
                a0 = fma2(eap[j][3], wB0.y, a0);
                unsigned long long a1 = fma2(eap[j][0], wA1.x, bq.y);
                a1 = fma2(eap[j][1], wA1.y, a1);
                a1 = fma2(eap[j][2], wB1.x, a1);
                a1 = fma2(eap[j][3], wB1.y, a1);
                float l0, h0, l1, h1;
                upk2(a0, l0, h0);
                upk2(a1, l1, h1);
                msg2[j] = fma2(xq.x, pk2(fmaxf(l0, 0.f), fmaxf(h0, 0.f)), msg2[j]);
                msg2[j] = fma2(xq.y, pk2(fmaxf(l1, 0.f), fmaxf(h1, 0.f)), msg2[j]);
            }
        }

        #pragma unroll
        for (int j = 0; j < ET; ++j) {
            float mlo, mhi;
            upk2(msg2[j], mlo, mhi);
            if (e0 + j < N_EDGES)
                atomicAdd(&g_agg[dst[j] * HID + lane], mlo + mhi);
        }
    }
    gdc_launch();
}

// ---------------------------------------------------------------------------
// Node update: h_out = relu(agg/max(cnt,1) + h_in @ root + bias)
// Each warp processes NT=4 consecutive nodes, fully unrolled and interleaved.
// Restores g_agg (and g_cnt when FIRST) to zero for the next layer / call.
// SEL input: 0 -> x param, 1 -> g_h1. OUTSEL: 1 -> g_h1, 2 -> g_h2.
// ---------------------------------------------------------------------------
template <int IN, int SEL, int OUTSEL, bool FIRST>
__global__ void __launch_bounds__(256)
node_kernel(const float* __restrict__ x,
            const float* __restrict__ root,   // [IN, HID]
            const float* __restrict__ bias)   // [HID]
{
    constexpr int NT = 4;
    __shared__ float rs[IN * HID];
    for (int i = threadIdx.x; i < IN * HID; i += blockDim.x) rs[i] = root[i];
    __syncthreads();

    gdc_wait();   // g_agg/g_cnt (edge/convert) and h-buffer from predecessors

    const int lane = (int)(threadIdx.x & 31u);
    const int w    = (int)((blockIdx.x * blockDim.x + threadIdx.x) >> 5);
    const int n0   = w * NT;
    if (n0 < N_NODES) {
        const float bv = bias[lane];

        int   nn[NT];
        bool  ok[NT];
        float inv[NT], hv[NT], acc[NT];

        #pragma unroll
        for (int t = 0; t < NT; ++t) {
            nn[t] = n0 + t;
            ok[t] = (nn[t] < N_NODES);
            nn[t] = ok[t] ? nn[t] : N_NODES - 1;   // clamp loads; stores guarded
        }
        #pragma unroll
        for (int t = 0; t < NT; ++t) {
            if (FIRST) {
                float c = g_cnt[nn[t]];
                inv[t] = 1.0f / fmaxf(c, 1.0f);
            } else {
                inv[t] = g_inv[nn[t]];
            }
            if (SEL == 0) hv[t] = x[nn[t] * IN + (lane & (IN - 1))];
            else          hv[t] = g_h1[nn[t] * IN + (lane & (IN - 1))];
            acc[t] = g_agg[nn[t] * HID + lane];
        }
        #pragma unroll
        for (int t = 0; t < NT; ++t) {
            if (FIRST && lane == 0 && ok[t]) {
                g_inv[nn[t]] = inv[t];
                g_cnt[nn[t]] = 0.0f;               // restore zero for next call
            }
            if (ok[t]) g_agg[nn[t] * HID + lane] = 0.0f;   // restore zero
            acc[t] = acc[t] * inv[t] + bv;
        }

        #pragma unroll
        for (int i = 0; i < IN; ++i) {
            #pragma unroll
            for (int t = 0; t < NT; ++t)
                acc[t] = fmaf(__shfl_sync(0xffffffffu, hv[t], i),
                              rs[i * HID + lane], acc[t]);
        }

        #pragma unroll
        for (int t = 0; t < NT; ++t) {
            if (ok[t]) {
                float r = fmaxf(acc[t], 0.0f);
                if (OUTSEL == 1) g_h1[nn[t] * HID + lane] = r;
                else             g_h2[nn[t] * HID + lane] = r;
            }
        }
    }
    gdc_launch();
}

// ---------------------------------------------------------------------------
// Layer-3 node update fused with output head, NT=4 nodes per warp.
// Also restores its g_agg slots to zero (invariant for the next call).
// ---------------------------------------------------------------------------
__global__ void __launch_bounds__(256)
node3_kernel(const float* __restrict__ root,    // [HID, HID]
             const float* __restrict__ bias,    // [HID]
             const float* __restrict__ w_out1,  // [HID, HID]
             const float* __restrict__ b_out1,  // [HID]
             const float* __restrict__ w_out2,  // [HID, 1]
             const float* __restrict__ b_out2,  // [1]
             float* __restrict__ out)
{
    constexpr int NT = 4;
    __shared__ float rs[HID * HID];
    __shared__ float wo[HID * HID];
    for (int i = threadIdx.x; i < HID * HID; i += blockDim.x) {
        rs[i] = root[i];
        wo[i] = w_out1[i];
    }
    __syncthreads();

    gdc_wait();   // g_agg (edge3), g_h2 (node2), g_inv (node1)

    const int lane = (int)(threadIdx.x & 31u);
    const int w    = (int)((blockIdx.x * blockDim.x + threadIdx.x) >> 5);
    const int n0   = w * NT;
    if (n0 >= N_NODES) return;
    const float bv  = bias[lane];
    const float b1v = b_out1[lane];
    const float w2v = w_out2[lane];
    const float b2v = b_out2[0];

    int   nn[NT];
    bool  ok[NT];
    float hv[NT], acc[NT];

    #pragma unroll
    for (int t = 0; t < NT; ++t) {
        nn[t] = n0 + t;
        ok[t] = (nn[t] < N_NODES);
        nn[t] = ok[t] ? nn[t] : N_NODES - 1;
    }
    #pragma unroll
    for (int t = 0; t < NT; ++t) {
        float inv = g_inv[nn[t]];
        acc[t] = g_agg[nn[t] * HID + lane] * inv + bv;
        hv[t]  = g_h2[nn[t] * HID + lane];
        if (ok[t]) g_agg[nn[t] * HID + lane] = 0.0f;   // restore zero
    }

    #pragma unroll
    for (int i = 0; i < HID; ++i) {
        #pragma unroll
        for (int t = 0; t < NT; ++t)
            acc[t] = fmaf(__shfl_sync(0xffffffffu, hv[t], i),
                          rs[i * HID + lane], acc[t]);
    }

    float h3[NT], acc2[NT];
    #pragma unroll
    for (int t = 0; t < NT; ++t) {
        h3[t]   = fmaxf(acc[t], 0.0f);
        acc2[t] = b1v;
    }

    #pragma unroll
    for (int o = 0; o < HID; ++o) {
        #pragma unroll
        for (int t = 0; t < NT; ++t)
            acc2[t] = fmaf(__shfl_sync(0xffffffffu, h3[t], o),
                           wo[o * HID + lane], acc2[t]);
    }

    #pragma unroll
    for (int t = 0; t < NT; ++t) {
        float v = fmaxf(acc2[t], 0.0f) * w2v;
        #pragma unroll
        for (int off = 16; off; off >>= 1)
            v += __shfl_xor_sync(0xffffffffu, v, off);
        if (lane == 0 && ok[t]) out[nn[t]] = v + b2v;
    }
}

// ---------------------------------------------------------------------------
// PDL launch helper: dependent kernels get programmaticStreamSerialization.
// ---------------------------------------------------------------------------
template <typename F, typename... Args>
static inline void launch_pdl(F f, int grid, int block, Args... args) {
    cudaLaunchConfig_t cfg = {};
    cfg.gridDim = dim3((unsigned)grid);
    cfg.blockDim = dim3((unsigned)block);
    cfg.dynamicSmemBytes = 0;
    cfg.stream = 0;
    cudaLaunchAttribute attr[1];
    attr[0].id = cudaLaunchAttributeProgrammaticStreamSerialization;
    attr[0].val.programmaticStreamSerializationAllowed = 1;
    cfg.attrs = attr;
    cfg.numAttrs = 1;
    cudaLaunchKernelEx(&cfg, f, args...);
}

// ---------------------------------------------------------------------------
extern "C" void kernel_launch(void* const* d_in, const int* in_sizes, int n_in,
                              void* d_out, int out_size)
{
    (void)in_sizes; (void)n_in; (void)out_size;

    const float* x      = (const float*)d_in[0];
    const void*  ei     = d_in[1];                 // dtype detected on device
    const float* ea     = (const float*)d_in[2];
    const float* w_mlp1 = (const float*)d_in[3];
    const float* b_mlp1 = (const float*)d_in[4];
    const float* root1  = (const float*)d_in[5];
    const float* bias1  = (const float*)d_in[6];
    const float* w_mlp2 = (const float*)d_in[7];
    const float* b_mlp2 = (const float*)d_in[8];
    const float* root2  = (const float*)d_in[9];
    const float* bias2  = (const float*)d_in[10];
    const float* w_mlp3 = (const float*)d_in[11];
    const float* b_mlp3 = (const float*)d_in[12];
    const float* root3  = (const float*)d_in[13];
    const float* bias3  = (const float*)d_in[14];
    const float* w_out1 = (const float*)d_in[15];
    const float* b_out1 = (const float*)d_in[16];
    const float* w_out2 = (const float*)d_in[17];
    const float* b_out2 = (const float*)d_in[18];
    float*       out    = (float*)d_out;

    const int DB = (N_EDGES + 255) / 256;            // per-edge blocks
    const int NB = (N_NODES + 31) / 32;              // node blocks: 8 warps x 4 nodes
    const int EB = 444;                              // edge blocks: one wave at 3/SM

    detect_kernel<<<DB, 256>>>(ei);                  // head of the PDL chain
    launch_pdl(convert_degree_kernel, DB, 256, ei);

    // Layer 1 (IN = 8): x -> g_h1
    launch_pdl(edge_kernel<NODE_IN, 0>, EB, 256, x, ea, w_mlp1, b_mlp1);
    launch_pdl(node_kernel<NODE_IN, 0, 1, true>, NB, 256, x, root1, bias1);

    // Layer 2 (IN = 32): g_h1 -> g_h2
    launch_pdl(edge_kernel<HID, 1>, EB, 256, x, ea, w_mlp2, b_mlp2);
    launch_pdl(node_kernel<HID, 1, 2, false>, NB, 256, x, root2, bias2);

    // Layer 3 (IN = 32) + fused output head: g_h2 -> out
    launch_pdl(edge_kernel<HID, 2>, EB, 256, x, ea, w_mlp3, b_mlp3);
    launch_pdl(node3_kernel, NB, 256, root3, bias3, w_out1, b_out1, w_out2, b_out2, out);
}

// round 17
// speedup vs baseline: 1.6708x; 1.6708x over previous
#include <cuda_runtime.h>

#define N_NODES 25000
#define N_EDGES 100000
#define NODE_IN 8
#define HID 32

// Scratch (device globals — allocation is forbidden). Zero-initialized at load;
// every kernel_launch call restores them to zero, so no per-call zeroing pass.
__device__ float g_h1[N_NODES * HID];
__device__ float g_h2[N_NODES * HID];
__device__ float g_agg[N_NODES * HID];
__device__ float g_cnt[N_NODES];
__device__ float g_inv[N_NODES];
__device__ int2  g_sd[N_EDGES];     // packed {src, dst}
__device__ int   g_bad64 = 0;       // raised (never lowered) if edge_index is int32

// ---------------------------------------------------------------------------
// PDL primitives (sm_90+)
// ---------------------------------------------------------------------------
__device__ __forceinline__ void gdc_wait()   { asm volatile("griddepcontrol.wait;" ::: "memory"); }
__device__ __forceinline__ void gdc_launch() { asm volatile("griddepcontrol.launch_dependents;" ::: "memory"); }

// ---------------------------------------------------------------------------
// Packed f32x2 helpers (Blackwell FFMA2 — only reachable via PTX)
// ---------------------------------------------------------------------------
__device__ __forceinline__ unsigned long long pk2(float lo, float hi) {
    unsigned long long r;
    asm("mov.b64 %0, {%1, %2};" : "=l"(r) : "f"(lo), "f"(hi));
    return r;
}
__device__ __forceinline__ void upk2(unsigned long long v, float& lo, float& hi) {
    asm("mov.b64 {%0, %1}, %2;" : "=f"(lo), "=f"(hi) : "l"(v));
}
__device__ __forceinline__ unsigned long long fma2(unsigned long long a,
                                                   unsigned long long b,
                                                   unsigned long long c) {
    unsigned long long d;
    asm("fma.rn.f32x2 %0, %1, %2, %3;" : "=l"(d) : "l"(a), "l"(b), "l"(c));
    return d;
}

// ---------------------------------------------------------------------------
// Detect index dtype (read-only, SAMPLED). Reads the first DETECT_N words as
// int64 — spans a prefix of the int32 buffer or the src half of an int64
// buffer, no OOB either way. int64 data: all sampled values in [0, N_NODES)
// -> flag stays 0. int32 data: packed pairs are out of range with huge margin
// across 8192 samples -> flag raised. Same-value store races benign; the flag
// is never lowered, so behavior is identical every call.
// ---------------------------------------------------------------------------
#define DETECT_N 8192
__global__ void detect_kernel(const void* __restrict__ ei) {
    int i = blockIdx.x * blockDim.x + threadIdx.x;
    if (i < DETECT_N) {
        long long v = ((const long long*)ei)[i];
        if (v < 0 || v >= N_NODES) g_bad64 = 1;
    }
    gdc_launch();
}

// ---------------------------------------------------------------------------
// Convert indices (dtype per flag, clamped) + accumulate in-degrees.
// g_cnt enters zeroed (node1 restored it at the end of the previous call).
// ---------------------------------------------------------------------------
__global__ void convert_degree_kernel(const void* __restrict__ ei) {
    gdc_wait();                                   // g_bad64 from detect
    int e = blockIdx.x * blockDim.x + threadIdx.x;
    if (e < N_EDGES) {
        const bool is64 = (g_bad64 == 0);
        long long s, d;
        if (is64) {
            s = ((const long long*)ei)[e];
            d = ((const long long*)ei)[N_EDGES + e];
        } else {
            s = ((const int*)ei)[e];
            d = ((const int*)ei)[N_EDGES + e];
        }
        int si = (int)s, di = (int)d;
        si = si < 0 ? 0 : (si >= N_NODES ? N_NODES - 1 : si);
        di = di < 0 ? 0 : (di >= N_NODES ? N_NODES - 1 : di);
        g_sd[e] = make_int2(si, di);
        atomicAdd(&g_cnt[di], 1.0f);
    }
    gdc_launch();
}

// ---------------------------------------------------------------------------
// Edge kernel: one warp per GROUP of ET=4 edges (grid-stride, tail-free).
// lane o computes msg[o] = sum_i h[src,i] * relu( ea . W[:, i*32+o] + b )
// All smem operands are LDS.128; x staged per warp (double-buffered).
// __launch_bounds__(256, 3): 3 blocks/SM resident; ET=4 is the largest tile
// that fits the 84-reg cap without hot-loop spills (ET=6 spilled: round 15).
// SEL: 0 -> x, 1 -> g_h1, 2 -> g_h2.
// ---------------------------------------------------------------------------
template <int IN, int SEL>
__global__ void __launch_bounds__(256, 3)
edge_kernel(const float* __restrict__ x,
            const float* __restrict__ ea,
            const float* __restrict__ w_mlp,  // [4, IN*HID] row-major
            const float* __restrict__ b_mlp)  // [IN*HID]
{
    constexpr int COLS  = IN * HID;
    constexpr int PAIRS = IN / 2;
    constexpr int PP    = PAIRS / 2;            // pair-pairs
    constexpr int ET    = 4;
    constexpr int NW    = 8;                    // warps per 256-thread block
    static_assert(N_EDGES % ET == 0, "tail-free");
    static_assert(PAIRS % 2 == 0, "even pair count");

    __shared__ ulonglong2 ws4[PAIRS * 2 * HID];
    __shared__ ulonglong2 bs4[PP * HID];
    __shared__ __align__(16) float xs[2][NW][ET * HID];  // double-buffered x rows

    // ---- independent prologue (external inputs only; overlaps via PDL) ----
    for (int idx = threadIdx.x; idx < PAIRS * 2 * HID; idx += blockDim.x) {
        int o = idx & (HID - 1);
        int q = (idx >> 5) & 1;
        int p = idx >> 6;
        ws4[idx] = make_ulonglong2(
            pk2(w_mlp[(2*q  )*COLS + (2*p)*HID + o], w_mlp[(2*q  )*COLS + (2*p+1)*HID + o]),
            pk2(w_mlp[(2*q+1)*COLS + (2*p)*HID + o], w_mlp[(2*q+1)*COLS + (2*p+1)*HID + o]));
    }
    for (int idx = threadIdx.x; idx < PP * HID; idx += blockDim.x) {
        int o  = idx & (HID - 1);
        int pp = idx >> 5;
        bs4[idx] = make_ulonglong2(
            pk2(b_mlp[(4*pp    )*HID + o], b_mlp[(4*pp + 1)*HID + o]),
            pk2(b_mlp[(4*pp + 2)*HID + o], b_mlp[(4*pp + 3)*HID + o]));
    }
    __syncthreads();

    gdc_wait();   // g_sd / h-buffer / zeroed g_agg from predecessors

    const int lane    = (int)(threadIdx.x & 31u);
    const int wl      = (int)(threadIdx.x >> 5);        // warp within block
    const int warp    = (int)((blockIdx.x * blockDim.x + threadIdx.x) >> 5);
    const int nwarps  = (int)((gridDim.x * blockDim.x) >> 5);
    const int ngroups = N_EDGES / ET;

    int buf = 0;
    for (int g = warp; g < ngroups; g += nwarps, buf ^= 1) {
        const int e0 = g * ET;

        int dst[ET];
        unsigned long long eap[ET][4];
        #pragma unroll
        for (int j = 0; j < ET; ++j) {
            const int e = e0 + j;
            const int2 sd = g_sd[e];
            dst[j] = sd.y;
            float4 v = *(const float4*)(ea + 4 * e);
            eap[j][0] = pk2(v.x, v.x);
            eap[j][1] = pk2(v.y, v.y);
            eap[j][2] = pk2(v.z, v.z);
            eap[j][3] = pk2(v.w, v.w);
            float xvj;
            if (SEL == 0)      xvj = x[sd.x * IN + (lane & (IN - 1))];
            else if (SEL == 1) xvj = g_h1[sd.x * IN + (lane & (IN - 1))];
            else               xvj = g_h2[sd.x * IN + (lane & (IN - 1))];
            xs[buf][wl][j * HID + lane] = xvj;
        }
        __syncwarp();
        const ulonglong2* xr = (const ulonglong2*)xs[buf][wl];

        unsigned long long msg2[ET];
        #pragma unroll
        for (int j = 0; j < ET; ++j) msg2[j] = 0ull;   // bits(0,0) == (0.f,0.f)

        #pragma unroll
        for (int pp = 0; pp < PP; ++pp) {
            const ulonglong2 bq  = bs4[pp * HID + lane];
            const ulonglong2 wA0 = ws4[(4*pp + 0) * HID + lane];
            const ulonglong2 wB0 = ws4[(4*pp + 1) * HID + lane];
            const ulonglong2 wA1 = ws4[(4*pp + 2) * HID + lane];
            const ulonglong2 wB1 = ws4[(4*pp + 3) * HID + lane];
            #pragma unroll
            for (int j = 0; j < ET; ++j) {
                const ulonglong2 xq = xr[j * (HID / 4) + pp];  // two x-pairs
                unsigned long long a0 = fma2(eap[j][0], wA0.x, bq.x);
                a0 = fma2(eap[j][1], wA0.y, a0);
                a0 = fma2(eap[j][2], wB0.x, a0);
                a0 = fma2(eap[j][3], wB0.y, a0);
                unsigned long long a1 = fma2(eap[j][0], wA1.x, bq.y);
                a1 = fma2(eap[j][1], wA1.y, a1);
                a1 = fma2(eap[j][2], wB1.x, a1);
                a1 = fma2(eap[j][3], wB1.y, a1);
                float l0, h0, l1, h1;
                upk2(a0, l0, h0);
                upk2(a1, l1, h1);
                msg2[j] = fma2(xq.x, pk2(fmaxf(l0, 0.f), fmaxf(h0, 0.f)), msg2[j]);
                msg2[j] = fma2(xq.y, pk2(fmaxf(l1, 0.f), fmaxf(h1, 0.f)), msg2[j]);
            }
        }

        #pragma unroll
        for (int j = 0; j < ET; ++j) {
            float mlo, mhi;
            upk2(msg2[j], mlo, mhi);
            atomicAdd(&g_agg[dst[j] * HID + lane], mlo + mhi);
        }
    }
    gdc_launch();
}

// ---------------------------------------------------------------------------
// Node update: h_out = relu(agg/max(cnt,1) + h_in @ root + bias)
// Each warp processes NT=4 consecutive nodes, fully unrolled and interleaved.
// Restores g_agg (and g_cnt when FIRST) to zero for the next layer / call.
// SEL input: 0 -> x param, 1 -> g_h1. OUTSEL: 1 -> g_h1, 2 -> g_h2.
// ---------------------------------------------------------------------------
template <int IN, int SEL, int OUTSEL, bool FIRST>
__global__ void __launch_bounds__(256)
node_kernel(const float* __restrict__ x,
            const float* __restrict__ root,   // [IN, HID]
            const float* __restrict__ bias)   // [HID]
{
    constexpr int NT = 4;
    __shared__ float rs[IN * HID];
    for (int i = threadIdx.x; i < IN * HID; i += blockDim.x) rs[i] = root[i];
    __syncthreads();

    gdc_wait();   // g_agg/g_cnt (edge/convert) and h-buffer from predecessors

    const int lane = (int)(threadIdx.x & 31u);
    const int w    = (int)((blockIdx.x * blockDim.x + threadIdx.x) >> 5);
    const int n0   = w * NT;
    if (n0 < N_NODES) {
        const float bv = bias[lane];

        int   nn[NT];
        bool  ok[NT];
        float inv[NT], hv[NT], acc[NT];

        #pragma unroll
        for (int t = 0; t < NT; ++t) {
            nn[t] = n0 + t;
            ok[t] = (nn[t] < N_NODES);
            nn[t] = ok[t] ? nn[t] : N_NODES - 1;   // clamp loads; stores guarded
        }
        #pragma unroll
        for (int t = 0; t < NT; ++t) {
            if (FIRST) {
                float c = g_cnt[nn[t]];
                inv[t] = 1.0f / fmaxf(c, 1.0f);
            } else {
                inv[t] = g_inv[nn[t]];
            }
            if (SEL == 0) hv[t] = x[nn[t] * IN + (lane & (IN - 1))];
            else          hv[t] = g_h1[nn[t] * IN + (lane & (IN - 1))];
            acc[t] = g_agg[nn[t] * HID + lane];
        }
        #pragma unroll
        for (int t = 0; t < NT; ++t) {
            if (FIRST && lane == 0 && ok[t]) {
                g_inv[nn[t]] = inv[t];
                g_cnt[nn[t]] = 0.0f;               // restore zero for next call
            }
            if (ok[t]) g_agg[nn[t] * HID + lane] = 0.0f;   // restore zero
            acc[t] = acc[t] * inv[t] + bv;
        }

        #pragma unroll
        for (int i = 0; i < IN; ++i) {
            #pragma unroll
            for (int t = 0; t < NT; ++t)
                acc[t] = fmaf(__shfl_sync(0xffffffffu, hv[t], i),
                              rs[i * HID + lane], acc[t]);
        }

        #pragma unroll
        for (int t = 0; t < NT; ++t) {
            if (ok[t]) {
                float r = fmaxf(acc[t], 0.0f);
                if (OUTSEL == 1) g_h1[nn[t] * HID + lane] = r;
                else             g_h2[nn[t] * HID + lane] = r;
            }
        }
    }
    gdc_launch();
}

// ---------------------------------------------------------------------------
// Layer-3 node update fused with output head, NT=4 nodes per warp.
// Also restores its g_agg slots to zero (invariant for the next call).
// ---------------------------------------------------------------------------
__global__ void __launch_bounds__(256)
node3_kernel(const float* __restrict__ root,    // [HID, HID]
             const float* __restrict__ bias,    // [HID]
             const float* __restrict__ w_out1,  // [HID, HID]
             const float* __restrict__ b_out1,  // [HID]
             const float* __restrict__ w_out2,  // [HID, 1]
             const float* __restrict__ b_out2,  // [1]
             float* __restrict__ out)
{
    constexpr int NT = 4;
    __shared__ float rs[HID * HID];
    __shared__ float wo[HID * HID];
    for (int i = threadIdx.x; i < HID * HID; i += blockDim.x) {
        rs[i] = root[i];
        wo[i] = w_out1[i];
    }
    __syncthreads();

    gdc_wait();   // g_agg (edge3), g_h2 (node2), g_inv (node1)

    const int lane = (int)(threadIdx.x & 31u);
    const int w    = (int)((blockIdx.x * blockDim.x + threadIdx.x) >> 5);
    const int n0   = w * NT;
    if (n0 >= N_NODES) return;
    const float bv  = bias[lane];
    const float b1v = b_out1[lane];
    const float w2v = w_out2[lane];
    const float b2v = b_out2[0];

    int   nn[NT];
    bool  ok[NT];
    float hv[NT], acc[NT];

    #pragma unroll
    for (int t = 0; t < NT; ++t) {
        nn[t] = n0 + t;
        ok[t] = (nn[t] < N_NODES);
        nn[t] = ok[t] ? nn[t] : N_NODES - 1;
    }
    #pragma unroll
    for (int t = 0; t < NT; ++t) {
        float inv = g_inv[nn[t]];
        acc[t] = g_agg[nn[t] * HID + lane] * inv + bv;
        hv[t]  = g_h2[nn[t] * HID + lane];
        if (ok[t]) g_agg[nn[t] * HID + lane] = 0.0f;   // restore zero
    }

    #pragma unroll
    for (int i = 0; i < HID; ++i) {
        #pragma unroll
        for (int t = 0; t < NT; ++t)
            acc[t] = fmaf(__shfl_sync(0xffffffffu, hv[t], i),
                          rs[i * HID + lane], acc[t]);
    }

    float h3[NT], acc2[NT];
    #pragma unroll
    for (int t = 0; t < NT; ++t) {
        h3[t]   = fmaxf(acc[t], 0.0f);
        acc2[t] = b1v;
    }

    #pragma unroll
    for (int o = 0; o < HID; ++o) {
        #pragma unroll
        for (int t = 0; t < NT; ++t)
            acc2[t] = fmaf(__shfl_sync(0xffffffffu, h3[t], o),
                           wo[o * HID + lane], acc2[t]);
    }

    #pragma unroll
    for (int t = 0; t < NT; ++t) {
        float v = fmaxf(acc2[t], 0.0f) * w2v;
        #pragma unroll
        for (int off = 16; off; off >>= 1)
            v += __shfl_xor_sync(0xffffffffu, v, off);
        if (lane == 0 && ok[t]) out[nn[t]] = v + b2v;
    }
}

// ---------------------------------------------------------------------------
// PDL launch helper: dependent kernels get programmaticStreamSerialization.
// ---------------------------------------------------------------------------
template <typename F, typename... Args>
static inline void launch_pdl(F f, int grid, int block, Args... args) {
    cudaLaunchConfig_t cfg = {};
    cfg.gridDim = dim3((unsigned)grid);
    cfg.blockDim = dim3((unsigned)block);
    cfg.dynamicSmemBytes = 0;
    cfg.stream = 0;
    cudaLaunchAttribute attr[1];
    attr[0].id = cudaLaunchAttributeProgrammaticStreamSerialization;
    attr[0].val.programmaticStreamSerializationAllowed = 1;
    cfg.attrs = attr;
    cfg.numAttrs = 1;
    cudaLaunchKernelEx(&cfg, f, args...);
}

// ---------------------------------------------------------------------------
extern "C" void kernel_launch(void* const* d_in, const int* in_sizes, int n_in,
                              void* d_out, int out_size)
{
    (void)in_sizes; (void)n_in; (void)out_size;

    const float* x      = (const float*)d_in[0];
    const void*  ei     = d_in[1];                 // dtype detected on device
    const float* ea     = (const float*)d_in[2];
    const float* w_mlp1 = (const float*)d_in[3];
    const float* b_mlp1 = (const float*)d_in[4];
    const float* root1  = (const float*)d_in[5];
    const float* bias1  = (const float*)d_in[6];
    const float* w_mlp2 = (const float*)d_in[7];
    const float* b_mlp2 = (const float*)d_in[8];
    const float* root2  = (const float*)d_in[9];
    const float* bias2  = (const float*)d_in[10];
    const float* w_mlp3 = (const float*)d_in[11];
    const float* b_mlp3 = (const float*)d_in[12];
    const float* root3  = (const float*)d_in[13];
    const float* bias3  = (const float*)d_in[14];
    const float* w_out1 = (const float*)d_in[15];
    const float* b_out1 = (const float*)d_in[16];
    const float* w_out2 = (const float*)d_in[17];
    const float* b_out2 = (const float*)d_in[18];
    float*       out    = (float*)d_out;

    const int TB = (DETECT_N + 255) / 256;           // detect blocks (sampled)
    const int DB = (N_EDGES + 255) / 256;            // per-edge blocks
    const int NB = (N_NODES + 31) / 32;              // node blocks: 8 warps x 4 nodes
    const int EB = 444;                              // edge blocks: one wave at 3/SM

    detect_kernel<<<TB, 256>>>(ei);                  // head of the PDL chain
    launch_pdl(convert_degree_kernel, DB, 256, ei);

    // Layer 1 (IN = 8): x -> g_h1
    launch_pdl(edge_kernel<NODE_IN, 0>, EB, 256, x, ea, w_mlp1, b_mlp1);
    launch_pdl(node_kernel<NODE_IN, 0, 1, true>, NB, 256, x, root1, bias1);

    // Layer 2 (IN = 32): g_h1 -> g_h2
    launch_pdl(edge_kernel<HID, 1>, EB, 256, x, ea, w_mlp2, b_mlp2);
    launch_pdl(node_kernel<HID, 1, 2, false>, NB, 256, x, root2, bias2);

    // Layer 3 (IN = 32) + fused output head: g_h2 -> out
    launch_pdl(edge_kernel<HID, 2>, EB, 256, x, ea, w_mlp3, b_mlp3);
    launch_pdl(node3_kernel, NB, 256, root3, bias3, w_out1, b_out1, w_out2, b_out2, out);
}